// round 8
// baseline (speedup 1.0000x reference)
#include <cuda_runtime.h>

// out[b,i,j,c1,c2,k]: k=0 -> x[b,i,c1,c2], k=1 -> x[b,j,c1,c2]
// B=64, GS=96, C=8. Tile (b,i) = 96 j-rows of 128 interleaved floats.
//
// Persistent grid: exactly 148*8 = 1184 CTAs (one full wave at 8 CTA/SM),
// grid-stride over the 6144 (b,i) tiles -> no wave-quantization tail
// (per-SM tile count 41-42 vs ideal 41.5).
// Per tile: 1 xi LDG.128 + 6 xj LDG.128, then 6 STG.256 streaming stores.

static constexpr int GS = 96;
static constexpr int ROW = 64;          // 8*8 floats per (b,g) block
static constexpr int NTILES = 64 * GS;  // 6144
static constexpr int NBLK = 148 * 8;    // 1184 persistent CTAs

__global__ void __launch_bounds__(256)
combo_kernel(const float* __restrict__ x, float* __restrict__ out)
{
    const int t = threadIdx.x;
    const int lane16 = t & 15;            // element-group within tile
    const int jbase  = t >> 4;            // 0..15

    for (int bi = blockIdx.x; bi < NTILES; bi += NBLK) {
        // xi: this thread's 4 elements of x[b,i], loop-invariant over j
        const float4 a =
            *reinterpret_cast<const float4*>(x + bi * ROW + lane16 * 4);

        const float* xb = x + (bi / GS) * GS * ROW;      // x[b, 0]
        float* outb = out + (size_t)bi * GS * 128;       // out[b, i, 0]

        // Preload all 6 xj vectors (independent loads, MLP=6)
        float4 c[6];
#pragma unroll
        for (int it = 0; it < 6; ++it) {
            const int j = jbase + it * 16;
            c[it] = *reinterpret_cast<const float4*>(xb + j * ROW + lane16 * 4);
        }

        // 6 back-to-back 256-bit streaming stores (evict-first: pure stream)
#pragma unroll
        for (int it = 0; it < 6; ++it) {
            const int j = jbase + it * 16;
            float* p = outb + j * 128 + lane16 * 8;
            asm volatile(
                "st.global.cs.v8.f32 [%0], {%1,%2,%3,%4,%5,%6,%7,%8};" ::
                "l"(p),
                "f"(a.x), "f"(c[it].x), "f"(a.y), "f"(c[it].y),
                "f"(a.z), "f"(c[it].z), "f"(a.w), "f"(c[it].w)
                : "memory");
        }
    }
}

extern "C" void kernel_launch(void* const* d_in, const int* in_sizes, int n_in,
                              void* d_out, int out_size)
{
    const float* x = (const float*)d_in[0];
    float* out = (float*)d_out;

    combo_kernel<<<NBLK, 256>>>(x, out);
}